// round 7
// baseline (speedup 1.0000x reference)
#include <cuda_runtime.h>
#include <cuda_fp16.h>
#include <cstdint>

#define NB 1024
#define NC 64
#define NI 40
#define NK 512
#define NP 20480   // NK * NI

// ---------------- device scratch (no allocation allowed) ----------------
__device__ __align__(16) __half g_xh[NI * NB * NC];           // [i][b][c]
__device__ __align__(16) __half g_ph[NI * NK * NC];           // [i][k][c]
__device__ __align__(16) float g_scls[NB * NK];               // class sums

// SW128 swizzle on byte offsets (128B rows)
#define SW128(o) ((o) ^ (((o) >> 3) & 0x70))

__device__ __forceinline__ uint32_t smem_u32(const void* p) {
    uint32_t a;
    asm("{ .reg .u64 t; cvta.to.shared.u64 t, %1; cvt.u32.u64 %0, t; }" : "=r"(a) : "l"(p));
    return a;
}
__device__ __forceinline__ void ldsm_x4(uint32_t* r, uint32_t addr) {
    asm volatile("ldmatrix.sync.aligned.m8n8.x4.shared.b16 {%0,%1,%2,%3}, [%4];"
                 : "=r"(r[0]), "=r"(r[1]), "=r"(r[2]), "=r"(r[3]) : "r"(addr));
}
__device__ __forceinline__ void mma16816(float* c, const uint32_t* a, const uint32_t* b) {
    asm volatile(
        "mma.sync.aligned.m16n8k16.row.col.f32.f16.f16.f32 "
        "{%0,%1,%2,%3}, {%4,%5,%6,%7}, {%8,%9}, {%0,%1,%2,%3};"
        : "+f"(c[0]), "+f"(c[1]), "+f"(c[2]), "+f"(c[3])
        : "r"(a[0]), "r"(a[1]), "r"(a[2]), "r"(a[3]), "r"(b[0]), "r"(b[1]));
}
__device__ __forceinline__ void cpa16(uint32_t s, const void* g) {
    asm volatile("{ .reg .u64 gg; cvta.to.global.u64 gg, %1; "
                 "cp.async.cg.shared.global [%0], [gg], 16; }"
                 :: "r"(s), "l"(g) : "memory");
}
#define CP_COMMIT() asm volatile("cp.async.commit_group;" ::: "memory")
#define CP_WAIT1()  asm volatile("cp.async.wait_group 1;" ::: "memory")
#define CP_WAIT0()  asm volatile("cp.async.wait_group 0;" ::: "memory")

// ---------------------------------------------------------------------------
// K1: normalize x over C, convert fp16, write [i=w][b][c]
// ---------------------------------------------------------------------------
__global__ void k_prep_x(const float* __restrict__ conv) {
    __shared__ float sx[NC * NI];
    __shared__ float sinv[NI];
    const int b = blockIdx.x, t = threadIdx.x;
    const float* src = conv + (size_t)b * NC * NI;
    for (int j = t; j < NC * NI; j += 256) sx[j] = src[j];
    __syncthreads();
    if (t < NI) {
        float ss = 0.f;
        #pragma unroll
        for (int c = 0; c < NC; c++) { float v = sx[c * NI + t]; ss += v * v; }
        sinv[t] = 1.f / fmaxf(sqrtf(ss), 1e-12f);
    }
    __syncthreads();
    for (int j = t; j < NI * NC; j += 256) {
        int w = j >> 6, c = j & 63;
        float val = sx[c * NI + w] * sinv[w];
        g_xh[((size_t)w * NB + b) * NC + c] = __float2half_rn(val);
    }
}

// ---------------------------------------------------------------------------
// K2: normalize prototypes over C, convert fp16, write [i][k][c]
// ---------------------------------------------------------------------------
__global__ void k_prep_p(const float* __restrict__ proto) {
    __shared__ float sq[256];
    __shared__ float sinv[4];
    const int t = threadIdx.x;
    const int p = blockIdx.x * 4 + (t >> 6);
    const int c = t & 63;
    float v = proto[(size_t)p * NC + c];
    sq[t] = v * v;
    __syncthreads();
    if ((t & 63) < 32) {
        float w = sq[t] + sq[t + 32];
        #pragma unroll
        for (int off = 16; off > 0; off >>= 1) w += __shfl_xor_sync(0xffffffffu, w, off);
        if ((t & 31) == 0) sinv[t >> 6] = 1.f / fmaxf(sqrtf(w), 1e-12f);
    }
    __syncthreads();
    float val = v * sinv[t >> 6];
    const int k = p / NI, i = p - k * NI;
    g_ph[((size_t)i * NK + k) * NC + c] = __float2half_rn(val);
}

// ---------------------------------------------------------------------------
// K3 (fused): per CTA: 32 b x 32 k x all 40 i.  256 threads, 8 warps
// = 2 i-slots x (2m x 2n), warp tile m16 n16 k64.  Triple-buffered cp.async
// (one __syncthreads per iter).  Results staged in smem [b][k*40+i], written
// coalesced to md; class sums kept in regs -> g_scls.
// ---------------------------------------------------------------------------
#define ST_STRIDE 1284                     // words per staging row (32 rows)
#define OFF_A     (32 * ST_STRIDE * 4)     // 164352
#define OFF_B     (OFF_A + 3 * 8192)       // 188928
#define FUSED_SMEM (OFF_B + 3 * 8192)      // 213504
#define CLS_STRIDE 33

__device__ __forceinline__ void issue_loads(uint32_t sb, int it, int buf,
                                            int t, int b0, int k0) {
    const int row = t >> 3, col = t & 7;
    const uint32_t sw = SW128(row * 128 + col * 16);
    #pragma unroll
    for (int q = 0; q < 2; q++) {
        const int i = 2 * it + q;
        cpa16(sb + OFF_A + buf * 8192 + q * 4096 + sw,
              g_xh + ((size_t)i * NB + b0 + row) * NC + col * 8);
        cpa16(sb + OFF_B + buf * 8192 + q * 4096 + sw,
              g_ph + ((size_t)i * NK + k0 + row) * NC + col * 8);
    }
}

__global__ void __launch_bounds__(256, 1) k_fused(float* __restrict__ md) {
    extern __shared__ float smf[];
    const uint32_t sb = smem_u32(smf);
    const int t = threadIdx.x, lane = t & 31, wid = t >> 5;
    const int iw = wid >> 2;                // i slot within pair
    const int wm = (wid >> 1) & 1, wn = wid & 1;
    const int b0 = blockIdx.x * 32;
    const int k0 = blockIdx.y * 32;

    // ldmatrix lane addressing
    const int r8 = lane & 7, g = lane >> 3;
    const uint32_t a_row = (uint32_t)(wm * 16 + (g & 1) * 8 + r8);
    const uint32_t a_kh  = (uint32_t)(g >> 1);
    const uint32_t b_row = (uint32_t)(wn * 16 + (g >> 1) * 8 + r8);
    const uint32_t b_kh  = (uint32_t)(g & 1);

    // output positions
    const int out_r  = wm * 16 + (lane >> 2);
    const int out_k  = wn * 16 + 2 * (lane & 3);

    float cs[8];
    #pragma unroll
    for (int q = 0; q < 8; q++) cs[q] = 0.f;

    issue_loads(sb, 0, 0, t, b0, k0); CP_COMMIT();
    issue_loads(sb, 1, 1, t, b0, k0); CP_COMMIT();

    #pragma unroll 1
    for (int it = 0; it < 20; it++) {
        if (it < 19) CP_WAIT1(); else CP_WAIT0();
        __syncthreads();                      // all warps done with buf (it-1)%3
        if (it < 18) {
            issue_loads(sb, it + 2, (it + 2) % 3, t, b0, k0);   // -> buf (it-1)%3
            CP_COMMIT();
        }

        const int buf = it % 3;
        const uint32_t Ab = sb + OFF_A + buf * 8192 + iw * 4096;
        const uint32_t Bb = sb + OFF_B + buf * 8192 + iw * 4096;

        uint32_t af[4][4], bf0[4][2], bf1[4][2];
        #pragma unroll
        for (int kc = 0; kc < 4; kc++) {
            ldsm_x4(af[kc], Ab + SW128(a_row * 128 + (kc * 2 + a_kh) * 16));
            uint32_t r[4];
            ldsm_x4(r, Bb + SW128(b_row * 128 + (kc * 2 + b_kh) * 16));
            bf0[kc][0] = r[0]; bf0[kc][1] = r[1];
            bf1[kc][0] = r[2]; bf1[kc][1] = r[3];
        }
        float acc0[4] = {0.f, 0.f, 0.f, 0.f};
        float acc1[4] = {0.f, 0.f, 0.f, 0.f};
        #pragma unroll
        for (int kc = 0; kc < 4; kc++) {
            mma16816(acc0, af[kc], bf0[kc]);
            mma16816(acc1, af[kc], bf1[kc]);
        }

        #pragma unroll
        for (int q = 0; q < 4; q++) { cs[q] += acc0[q]; cs[4 + q] += acc1[q]; }

        // stage into [b][k*40+i]
        const int i = 2 * it + iw;
        smf[out_r * ST_STRIDE + out_k * NI + i]              = acc0[0];
        smf[out_r * ST_STRIDE + (out_k + 1) * NI + i]        = acc0[1];
        smf[(out_r + 8) * ST_STRIDE + out_k * NI + i]        = acc0[2];
        smf[(out_r + 8) * ST_STRIDE + (out_k + 1) * NI + i]  = acc0[3];
        smf[out_r * ST_STRIDE + (out_k + 8) * NI + i]        = acc1[0];
        smf[out_r * ST_STRIDE + (out_k + 9) * NI + i]        = acc1[1];
        smf[(out_r + 8) * ST_STRIDE + (out_k + 8) * NI + i]  = acc1[2];
        smf[(out_r + 8) * ST_STRIDE + (out_k + 9) * NI + i]  = acc1[3];
    }
    __syncthreads();   // staging complete; A/B buffers now dead -> reuse for cls

    // ---- class sums: per-iw partials to (dead) A-buffer smem, combine ----
    float* clsb = smf + OFF_A / 4;
    clsb[iw * 32 * CLS_STRIDE + out_r * CLS_STRIDE + out_k]           = cs[0];
    clsb[iw * 32 * CLS_STRIDE + out_r * CLS_STRIDE + out_k + 1]       = cs[1];
    clsb[iw * 32 * CLS_STRIDE + (out_r + 8) * CLS_STRIDE + out_k]     = cs[2];
    clsb[iw * 32 * CLS_STRIDE + (out_r + 8) * CLS_STRIDE + out_k + 1] = cs[3];
    clsb[iw * 32 * CLS_STRIDE + out_r * CLS_STRIDE + out_k + 8]       = cs[4];
    clsb[iw * 32 * CLS_STRIDE + out_r * CLS_STRIDE + out_k + 9]       = cs[5];
    clsb[iw * 32 * CLS_STRIDE + (out_r + 8) * CLS_STRIDE + out_k + 8] = cs[6];
    clsb[iw * 32 * CLS_STRIDE + (out_r + 8) * CLS_STRIDE + out_k + 9] = cs[7];
    __syncthreads();

    {
        const int r = t >> 3, kq = (t & 7) * 4;
        float4 v;
        v.x = clsb[r * CLS_STRIDE + kq]     + clsb[32 * CLS_STRIDE + r * CLS_STRIDE + kq];
        v.y = clsb[r * CLS_STRIDE + kq + 1] + clsb[32 * CLS_STRIDE + r * CLS_STRIDE + kq + 1];
        v.z = clsb[r * CLS_STRIDE + kq + 2] + clsb[32 * CLS_STRIDE + r * CLS_STRIDE + kq + 2];
        v.w = clsb[r * CLS_STRIDE + kq + 3] + clsb[32 * CLS_STRIDE + r * CLS_STRIDE + kq + 3];
        *reinterpret_cast<float4*>(&g_scls[(size_t)(b0 + r) * NK + k0 + kq]) = v;
    }

    // ---- md write: coalesced float4 of contiguous 1280-float runs ----
    for (int m = t; m < 32 * 320; m += 256) {
        const int row = m / 320;
        const int off = m - row * 320;
        float4 v = *reinterpret_cast<const float4*>(&smf[row * ST_STRIDE + off * 4]);
        __stcs(reinterpret_cast<float4*>(md + (size_t)(b0 + row) * NP + k0 * NI + off * 4),
               make_float4(-v.x, -v.y, -v.z, -v.w));
    }
}

// ---------------------------------------------------------------------------
// K4: logits[b][cls] = 1.5*S_cls - 0.5*S_total.  4 batches per block (MLP 4).
// ---------------------------------------------------------------------------
__global__ void __launch_bounds__(512) k_logits(float* __restrict__ out) {
    __shared__ float ws[4][16];
    __shared__ float tot[4];
    const int bq = blockIdx.x * 4;
    const int t = threadIdx.x;           // t = k
    float s[4];
    #pragma unroll
    for (int j = 0; j < 4; j++) s[j] = g_scls[(size_t)(bq + j) * NK + t];

    #pragma unroll
    for (int j = 0; j < 4; j++) {
        float w = s[j];
        #pragma unroll
        for (int off = 16; off > 0; off >>= 1) w += __shfl_xor_sync(0xffffffffu, w, off);
        if ((t & 31) == 0) ws[j][t >> 5] = w;
    }
    __syncthreads();
    if (t < 64) {
        const int j = t >> 4;
        float u = ws[j][t & 15];
        #pragma unroll
        for (int off = 8; off > 0; off >>= 1) u += __shfl_xor_sync(0xffffffffu, u, off);
        if ((t & 15) == 0) tot[j] = u;
    }
    __syncthreads();
    #pragma unroll
    for (int j = 0; j < 4; j++)
        out[(size_t)(bq + j) * NK + t] = 1.5f * s[j] - 0.5f * tot[j];
}

// ---------------------------------------------------------------------------
extern "C" void kernel_launch(void* const* d_in, const int* in_sizes, int n_in,
                              void* d_out, int out_size) {
    const float* conv  = (const float*)d_in[0];   // (1024, 64, 1, 40)
    const float* proto = (const float*)d_in[1];   // (20480, 64, 1, 1)
    // d_in[2], d_in[3] analytic — unused.

    float* out    = (float*)d_out;
    float* logits = out;                                // (1024, 512)
    float* md     = out + (size_t)NB * NK;              // (1024, 20480)

    cudaFuncSetAttribute(k_fused, cudaFuncAttributeMaxDynamicSharedMemorySize, FUSED_SMEM);

    k_prep_x<<<NB, 256>>>(conv);
    k_prep_p<<<NP / 4, 256>>>(proto);
    k_fused<<<dim3(NB / 32, NK / 32), 256, FUSED_SMEM>>>(md);
    k_logits<<<NB / 4, 512>>>(logits);
}